// round 15
// baseline (speedup 1.0000x reference)
#include <cuda_runtime.h>
#include <cstdint>

// FNNKernelTransform via mma.sync (m16n8k8 tf32) — family-common PTX, no tcgen05.
//
//   b3 is folded into the last GEMM:  A = [h2 | 1 | 0..0] (K=136),
//   B = [W3 ; b3 ; 0..0]  =>  K-chunk = A @ B already includes bias.
//   Epilogue: out[e,i] = sum_j Kchunk[e, i-block col j] * v'[e,j],
//   v' = [v(32), 1.0, 0x7] per edge.
//
//   Smem A/B use a k-interleaved layout (k' = 2*(k%4) + k/4 within each 8-group)
//   so every mma operand fragment is a single conflict-free LDS.64 (stride 136).

#define NT       256
#define TILE_E   128
#define KA       136            // augmented K (128 + 1 ones + 7 pad), also smem stride
#define NCH      8
#define CHN      160            // 4 padded (40-wide) i-blocks per chunk
#define E_TOTAL  262144

// smem float offsets
#define A_OFF    0              // [128][136] = 17408
#define B_OFF    17408          // [160][136] = 21760
#define VS_OFF   39168          // [128][40]  = 5120
#define OS_OFF   44288          // [128][33]  = 4224
#define SMEM_FLOATS 48512
#define SMEM_BYTES  (SMEM_FLOATS * 4)   // 194048

// k-interleave within 8-group: (k, k+4) become adjacent -> LDS.64 fragments
#define ILV(k) ( ((k) & ~7) | (((k) & 3) << 1) | (((k) >> 2) & 1) )

__device__ __align__(16) float g_W2t[128 * KA];          // [n][k'] tf32
__device__ __align__(16) float g_W3t[NCH * CHN * KA];    // [chunk][p][k'] tf32 (+b3 row)

__device__ __forceinline__ uint32_t tf32r(float x) {
    uint32_t u;
    asm("cvt.rn.tf32.f32 %0, %1;" : "=r"(u) : "f"(x));
    return u;
}
__device__ __forceinline__ void mma8(float* d, const uint32_t* a, uint32_t b0, uint32_t b1) {
    asm volatile(
        "mma.sync.aligned.m16n8k8.row.col.f32.tf32.tf32.f32 "
        "{%0,%1,%2,%3}, {%4,%5,%6,%7}, {%8,%9}, {%0,%1,%2,%3};"
        : "+f"(d[0]), "+f"(d[1]), "+f"(d[2]), "+f"(d[3])
        : "r"(a[0]), "r"(a[1]), "r"(a[2]), "r"(a[3]), "r"(b0), "r"(b1));
}

// ------------------------------------------------------------------ prep ----
__global__ void prep_w2(const float* __restrict__ W2) {
    int idx = blockIdx.x * blockDim.x + threadIdx.x;     // 128*136
    if (idx >= 128 * KA) return;
    int n = idx / KA, kk = idx % KA;
    int k = (kk & ~7) + ((kk & 7) >> 1) + 4 * (kk & 1);  // de-interleave
    float val = (k < 128) ? W2[k * 128 + n] : 0.0f;
    g_W2t[idx] = __uint_as_float(tf32r(val));
}
__global__ void prep_w3(const float* __restrict__ W3, const float* __restrict__ b3) {
    int idx = blockIdx.x * blockDim.x + threadIdx.x;     // 8*160*136
    if (idx >= NCH * CHN * KA) return;
    int c   = idx / (CHN * KA);
    int rem = idx - c * (CHN * KA);
    int p = rem / KA, kk = rem % KA;
    int k = (kk & ~7) + ((kk & 7) >> 1) + 4 * (kk & 1);
    int gcol = c * CHN + p;
    int i = gcol / 40, j = gcol % 40;
    float val = 0.0f;
    if (j < 33) {
        if (k < 128)       val = W3[k * 1056 + i * 33 + j];
        else if (k == 128) val = b3[i * 33 + j];
    }
    g_W3t[idx] = __uint_as_float(tf32r(val));
}

// ------------------------------------------------------------------ main ----
__global__ __launch_bounds__(NT, 1)
void fnn_mma_kernel(const float* __restrict__ pos_i, const float* __restrict__ pos_j,
                    const float* __restrict__ v,
                    const float* __restrict__ W1, const float* __restrict__ b1,
                    const float* __restrict__ b2,
                    float* __restrict__ out) {
    extern __shared__ float sm[];
    float* As = sm + A_OFF;
    float* Bs = sm + B_OFF;
    float* vs = sm + VS_OFF;
    float* os = sm + OS_OFF;

    const int tid  = threadIdx.x;
    const int warp = tid >> 5;
    const int lane = tid & 31;
    const int q    = lane >> 2;      // quad id (row within m16 half)
    const int t    = lane & 3;       // thread-in-quad (k / col pairing)
    const int mg   = warp >> 2;      // 0..1 -> 64-row band
    const int ng   = warp & 3;       // 0..3
    const int mbase = mg * 64;
    const int ebase = blockIdx.x * TILE_E;

    // ---- stage v' [128][40]: v, 1.0 at j=32, 0 at j>=33 --------------------
#pragma unroll
    for (int r = 0; r < 20; r++) {
        int idx = tid + NT * r;                  // 5120
        int e = idx / 40, j = idx - e * 40;
        vs[idx] = (j < 32) ? v[(ebase + e) * 32 + j] : (j == 32 ? 1.0f : 0.0f);
    }
    // ---- copy W2t -> Bs (straight) -----------------------------------------
    {
        float4* B4 = (float4*)Bs;
        const float4* s4 = (const float4*)g_W2t;
#pragma unroll
        for (int r = 0; r < 17; r++) B4[tid + NT * r] = s4[tid + NT * r];
    }
    __syncthreads();

    // ---- h1 = relu(x @ W1 + b1) -> As (tf32, interleaved) ------------------
    {
        int e = tid >> 1, half = tid & 1;
        float x0 = pos_i[(ebase + e) * 2];
        float x1 = pos_i[(ebase + e) * 2 + 1];
        float x2 = pos_j[(ebase + e) * 2];
        float x3 = pos_j[(ebase + e) * 2 + 1];
#pragma unroll 8
        for (int oo = 0; oo < 64; oo++) {
            int o = half * 64 + oo;
            float acc = __ldg(b1 + o);
            acc = fmaf(x0, __ldg(W1 + o),       acc);
            acc = fmaf(x1, __ldg(W1 + 128 + o), acc);
            acc = fmaf(x2, __ldg(W1 + 256 + o), acc);
            acc = fmaf(x3, __ldg(W1 + 384 + o), acc);
            As[e * KA + ILV(o)] = __uint_as_float(tf32r(fmaxf(acc, 0.0f)));
        }
        // augmented cols 128..135: 1.0 at kk=128 (k=128), else 0
#pragma unroll
        for (int r = 0; r < 4; r++) {
            int idx = tid + NT * r;              // 1024
            int ee = idx >> 3, kk8 = idx & 7;
            As[ee * KA + 128 + kk8] = (kk8 == 0) ? 1.0f : 0.0f;
        }
    }
    __syncthreads();

    // ---- phase 1: h2 = relu(h1 @ W2 + b2)  (M=128 N=128 K=128) -------------
    {
        float acc1[4][4][4];
#pragma unroll
        for (int mt = 0; mt < 4; mt++)
#pragma unroll
            for (int nt = 0; nt < 4; nt++)
#pragma unroll
                for (int x = 0; x < 4; x++) acc1[mt][nt][x] = 0.0f;
        const int nbase1 = ng * 32;

#pragma unroll 4
        for (int kg = 0; kg < 16; kg++) {
            uint32_t a[4][4];
#pragma unroll
            for (int mt = 0; mt < 4; mt++) {
                int r0 = mbase + mt * 16 + q;
                uint2 a02 = *(const uint2*)(As + r0 * KA + kg * 8 + 2 * t);
                uint2 a13 = *(const uint2*)(As + (r0 + 8) * KA + kg * 8 + 2 * t);
                a[mt][0] = a02.x; a[mt][1] = a13.x; a[mt][2] = a02.y; a[mt][3] = a13.y;
            }
#pragma unroll
            for (int nt = 0; nt < 4; nt++) {
                int n = nbase1 + nt * 8 + q;
                uint2 b01 = *(const uint2*)(Bs + n * KA + kg * 8 + 2 * t);
#pragma unroll
                for (int mt = 0; mt < 4; mt++) mma8(acc1[mt][nt], a[mt], b01.x, b01.y);
            }
        }
        __syncthreads();          // everyone done reading As before overwrite
        // writeback h2 (+b2, relu, tf32) into As, interleaved
#pragma unroll
        for (int mt = 0; mt < 4; mt++) {
#pragma unroll
            for (int nt = 0; nt < 4; nt++) {
                int r0 = mbase + mt * 16 + q;
                int o0 = nbase1 + nt * 8 + 2 * t;
                float bb0 = __ldg(b2 + o0), bb1 = __ldg(b2 + o0 + 1);
                As[r0 * KA + ILV(o0)] =
                    __uint_as_float(tf32r(fmaxf(acc1[mt][nt][0] + bb0, 0.0f)));
                As[r0 * KA + ILV(o0 + 1)] =
                    __uint_as_float(tf32r(fmaxf(acc1[mt][nt][1] + bb1, 0.0f)));
                As[(r0 + 8) * KA + ILV(o0)] =
                    __uint_as_float(tf32r(fmaxf(acc1[mt][nt][2] + bb0, 0.0f)));
                As[(r0 + 8) * KA + ILV(o0 + 1)] =
                    __uint_as_float(tf32r(fmaxf(acc1[mt][nt][3] + bb1, 0.0f)));
            }
        }
    }
    __syncthreads();

    // ---- phase 2: K-chunks = [h2|1] @ [W3;b3], contract with v' ------------
    const int nbase2 = ng * 40;          // this warp's padded i-block in chunk
    for (int c = 0; c < NCH; c++) {
        // stage B chunk (straight copy of pre-laid-out image)
        {
            float4* B4 = (float4*)Bs;
            const float4* w4 = (const float4*)(g_W3t + c * (CHN * KA));
#pragma unroll
            for (int r = 0; r < 21; r++) B4[tid + NT * r] = w4[tid + NT * r];
            if (tid < 64) B4[tid + 21 * NT] = w4[tid + 21 * NT];
        }
        __syncthreads();

        float acc[4][5][4];
#pragma unroll
        for (int mt = 0; mt < 4; mt++)
#pragma unroll
            for (int nt = 0; nt < 5; nt++)
#pragma unroll
                for (int x = 0; x < 4; x++) acc[mt][nt][x] = 0.0f;

#pragma unroll 4
        for (int kg = 0; kg < 17; kg++) {
            uint32_t a[4][4];
#pragma unroll
            for (int mt = 0; mt < 4; mt++) {
                int r0 = mbase + mt * 16 + q;
                uint2 a02 = *(const uint2*)(As + r0 * KA + kg * 8 + 2 * t);
                uint2 a13 = *(const uint2*)(As + (r0 + 8) * KA + kg * 8 + 2 * t);
                a[mt][0] = a02.x; a[mt][1] = a13.x; a[mt][2] = a02.y; a[mt][3] = a13.y;
            }
#pragma unroll
            for (int nt = 0; nt < 5; nt++) {
                int n = nbase2 + nt * 8 + q;
                uint2 b01 = *(const uint2*)(Bs + n * KA + kg * 8 + 2 * t);
#pragma unroll
                for (int mt = 0; mt < 4; mt++) mma8(acc[mt][nt], a[mt], b01.x, b01.y);
            }
        }

        // epilogue: contract fragments with v' (i-block = c*4 + ng)
        const int iblk = c * 4 + ng;
#pragma unroll
        for (int mt = 0; mt < 4; mt++) {
            int e0 = mbase + mt * 16 + q;
            float s0 = 0.0f, s1 = 0.0f;
#pragma unroll
            for (int nt = 0; nt < 5; nt++) {
                int col = nt * 8 + 2 * t;        // col within 40-wide block
                float2 vp0 = *(const float2*)(vs + e0 * 40 + col);
                float2 vp1 = *(const float2*)(vs + (e0 + 8) * 40 + col);
                s0 = fmaf(acc[mt][nt][0], vp0.x, s0);
                s0 = fmaf(acc[mt][nt][1], vp0.y, s0);
                s1 = fmaf(acc[mt][nt][2], vp1.x, s1);
                s1 = fmaf(acc[mt][nt][3], vp1.y, s1);
            }
            s0 += __shfl_xor_sync(0xFFFFFFFFu, s0, 1);
            s0 += __shfl_xor_sync(0xFFFFFFFFu, s0, 2);
            s1 += __shfl_xor_sync(0xFFFFFFFFu, s1, 1);
            s1 += __shfl_xor_sync(0xFFFFFFFFu, s1, 2);
            if (t == 0) {
                os[e0 * 33 + iblk]       = s0;
                os[(e0 + 8) * 33 + iblk] = s1;
            }
        }
        __syncthreads();           // all B reads + os writes done before next chunk
    }

    // ---- coalesced output ---------------------------------------------------
#pragma unroll
    for (int r = 0; r < 16; r++) {
        int idx = tid + NT * r;                 // 4096
        int e = idx >> 5, i = idx & 31;
        out[(ebase + e) * 32 + i] = os[e * 33 + i];
    }
}

extern "C" void kernel_launch(void* const* d_in, const int* in_sizes, int n_in,
                              void* d_out, int out_size) {
    const float* pos_i = (const float*)d_in[0];
    const float* pos_j = (const float*)d_in[1];
    const float* v     = (const float*)d_in[2];
    const float* W1    = (const float*)d_in[3];
    const float* b1    = (const float*)d_in[4];
    const float* W2    = (const float*)d_in[5];
    const float* b2    = (const float*)d_in[6];
    const float* W3    = (const float*)d_in[7];
    const float* b3    = (const float*)d_in[8];
    float* out = (float*)d_out;

    prep_w2<<<(128 * KA + NT - 1) / NT, NT>>>(W2);
    prep_w3<<<(NCH * CHN * KA + NT - 1) / NT, NT>>>(W3, b3);

    cudaFuncSetAttribute(fnn_mma_kernel,
                         cudaFuncAttributeMaxDynamicSharedMemorySize, SMEM_BYTES);
    fnn_mma_kernel<<<E_TOTAL / TILE_E, NT, SMEM_BYTES>>>(
        pos_i, pos_j, v, W1, b1, b2, out);
}

// round 16
// speedup vs baseline: 1.7146x; 1.7146x over previous
#include <cuda_runtime.h>
#include <cuda_fp16.h>
#include <cstdint>

// FNNKernelTransform via mma.sync m16n8k16 f16 (fp32 accum) + cp.async pipelining.
//   b3 folded into last GEMM: A = [h2 | 1 | 0..] (K=144), B = [W3 ; b3 ; 0..].
//   out[e,i] = sum_j Kchunk[e, iblk col j] * v'[e,j],  v' = [v(32), 1.0, 0*7].
//   Half-precision smem with per-16 k-interleave (0,1,8,9,2,3,10,11,...) so each
//   mma operand fragment is one conflict-free LDS.64 (row stride 288B).

#define NT       256
#define TILE_E   128
#define KAH      144            // halfs per row (128 + 1 ones + 15 pad)
#define RB       288            // row bytes
#define NCH      8
#define CHN      160            // 4 padded (40-wide) i-blocks per chunk
#define E_TOTAL  262144

// smem byte offsets
#define A_OFF    0              // 128*288 = 36864
#define B0_OFF   36864          // 160*288 = 46080
#define B1_OFF   82944          // 46080
#define VS_OFF   129024         // float [128][40] = 20480
#define OS_OFF   149504         // float [128][33] = 16896
#define SMEM_BYTES 166400

__device__ __align__(16) __half g_W2t[128 * KAH];        // [n][k'] f16
__device__ __align__(16) __half g_W3t[NCH * CHN * KAH];  // [chunk][p][k'] f16 (+b3 row)

// interleave: cols {2t,2t+1,2t+8,2t+9} contiguous (8B per thread)
__device__ __host__ __forceinline__ int ilv16(int c) {
    int g = c & ~15, r = c & 15;
    int p = (r < 8) ? ((r >> 1) * 4 + (r & 1)) : (((r - 8) >> 1) * 4 + 2 + (r & 1));
    return g + p;
}
__device__ __forceinline__ int invilv(int p) {
    int g = p & ~15, r = p & 15, b = r & 3;
    int c = (b < 2) ? ((r >> 2) * 2 + (b & 1)) : (8 + (r >> 2) * 2 + (b & 1));
    return g + c;
}
__device__ __forceinline__ void mmaf16(float* d, const uint32_t* a, uint32_t b0, uint32_t b1) {
    asm volatile(
        "mma.sync.aligned.m16n8k16.row.col.f32.f16.f16.f32 "
        "{%0,%1,%2,%3}, {%4,%5,%6,%7}, {%8,%9}, {%0,%1,%2,%3};"
        : "+f"(d[0]), "+f"(d[1]), "+f"(d[2]), "+f"(d[3])
        : "r"(a[0]), "r"(a[1]), "r"(a[2]), "r"(a[3]), "r"(b0), "r"(b1));
}
__device__ __forceinline__ void cpa16(uint32_t s, const void* g) {
    asm volatile("cp.async.cg.shared.global [%0], [%1], 16;" :: "r"(s), "l"(g));
}
#define CP_COMMIT() asm volatile("cp.async.commit_group;" ::: "memory")
#define CP_WAIT0()  asm volatile("cp.async.wait_group 0;" ::: "memory")
#define CP_WAIT1()  asm volatile("cp.async.wait_group 1;" ::: "memory")

// ------------------------------------------------------------------ prep ----
__global__ void prep_w2(const float* __restrict__ W2) {
    int idx = blockIdx.x * blockDim.x + threadIdx.x;
    if (idx >= 128 * KAH) return;
    int n = idx / KAH, kk = idx % KAH;
    int k = invilv(kk);
    float val = (k < 128) ? W2[k * 128 + n] : 0.0f;
    g_W2t[idx] = __float2half_rn(val);
}
__global__ void prep_w3(const float* __restrict__ W3, const float* __restrict__ b3) {
    int idx = blockIdx.x * blockDim.x + threadIdx.x;
    if (idx >= NCH * CHN * KAH) return;
    int c   = idx / (CHN * KAH);
    int rem = idx - c * (CHN * KAH);
    int p = rem / KAH, kk = rem % KAH;
    int k = invilv(kk);
    int gcol = c * CHN + p;
    int i = gcol / 40, j = gcol % 40;
    float val = 0.0f;
    if (j < 33) {
        if (k < 128)       val = W3[k * 1056 + i * 33 + j];
        else if (k == 128) val = b3[i * 33 + j];
    }
    g_W3t[idx] = __float2half_rn(val);
}

// ------------------------------------------------------------------ main ----
__global__ __launch_bounds__(NT, 1)
void fnn_mma_kernel(const float* __restrict__ pos_i, const float* __restrict__ pos_j,
                    const float* __restrict__ v,
                    const float* __restrict__ W1, const float* __restrict__ b1,
                    const float* __restrict__ b2,
                    float* __restrict__ out) {
    extern __shared__ char sm8[];
    char*  smA = sm8 + A_OFF;
    float* vs  = (float*)(sm8 + VS_OFF);
    float* os  = (float*)(sm8 + OS_OFF);
    const uint32_t sb = (uint32_t)__cvta_generic_to_shared(sm8);

    const int tid  = threadIdx.x;
    const int warp = tid >> 5;
    const int lane = tid & 31;
    const int q    = lane >> 2;
    const int t    = lane & 3;
    const int mg   = warp >> 2;      // 0..1 -> 64-row band
    const int ng   = warp & 3;
    const int mbase = mg * 64;
    const int ebase = blockIdx.x * TILE_E;

    // ---- prologue async copies: chunk0 -> B0, W2t -> B1 --------------------
#pragma unroll
    for (int r = 0; r < 12; r++) {
        int idx = tid + NT * r;                         // 2880 x 16B
        if (idx < 2880) cpa16(sb + B0_OFF + idx * 16, (const char*)g_W3t + idx * 16);
    }
#pragma unroll
    for (int r = 0; r < 9; r++) {                       // 2304 x 16B
        int idx = tid + NT * r;
        cpa16(sb + B1_OFF + idx * 16, (const char*)g_W2t + idx * 16);
    }
    CP_COMMIT();

    // ---- stage v' [128][40] ------------------------------------------------
#pragma unroll
    for (int r = 0; r < 20; r++) {
        int idx = tid + NT * r;
        int e = idx / 40, j = idx - e * 40;
        vs[idx] = (j < 32) ? v[(ebase + e) * 32 + j] : (j == 32 ? 1.0f : 0.0f);
    }
    // ---- A ones region (k = 128..143): 1.0 at k=128 ------------------------
#pragma unroll
    for (int r = 0; r < 4; r++) {
        int idx = tid + NT * r;                         // 1024 x 4B
        int e = idx >> 3, pp = idx & 7;
        *(uint32_t*)(smA + e * RB + 256 + pp * 4) = (pp == 0) ? 0x00003C00u : 0u;
    }
    // ---- h1 = relu(x @ W1 + b1) -> A (fp16, interleaved) -------------------
    {
        int e = tid >> 1, hf = tid & 1;
        float x0 = pos_i[(ebase + e) * 2];
        float x1 = pos_i[(ebase + e) * 2 + 1];
        float x2 = pos_j[(ebase + e) * 2];
        float x3 = pos_j[(ebase + e) * 2 + 1];
#pragma unroll 8
        for (int oo = 0; oo < 64; oo += 2) {
            int o = hf * 64 + oo;
            float a0 = __ldg(b1 + o), a1 = __ldg(b1 + o + 1);
            a0 = fmaf(x0, __ldg(W1 + o),       a0);  a1 = fmaf(x0, __ldg(W1 + o + 1),       a1);
            a0 = fmaf(x1, __ldg(W1 + 128 + o), a0);  a1 = fmaf(x1, __ldg(W1 + 129 + o),     a1);
            a0 = fmaf(x2, __ldg(W1 + 256 + o), a0);  a1 = fmaf(x2, __ldg(W1 + 257 + o),     a1);
            a0 = fmaf(x3, __ldg(W1 + 384 + o), a0);  a1 = fmaf(x3, __ldg(W1 + 385 + o),     a1);
            *(half2*)(smA + e * RB + ilv16(o) * 2) =
                __floats2half2_rn(fmaxf(a0, 0.0f), fmaxf(a1, 0.0f));
        }
    }
    CP_WAIT0();
    __syncthreads();

    // ---- phase 1: h2 = relu(h1 @ W2 + b2) ----------------------------------
    {
        const char* Bp = sm8 + B1_OFF;
        float acc1[4][4][4];
#pragma unroll
        for (int mt = 0; mt < 4; mt++)
#pragma unroll
            for (int nt = 0; nt < 4; nt++)
#pragma unroll
                for (int x = 0; x < 4; x++) acc1[mt][nt][x] = 0.0f;
        const int nbase1 = ng * 32;
#pragma unroll 4
        for (int kg = 0; kg < 8; kg++) {
            uint32_t a[4][4];
#pragma unroll
            for (int mt = 0; mt < 4; mt++) {
                int r0 = mbase + mt * 16 + q;
                uint2 u0 = *(const uint2*)(smA + r0 * RB + kg * 32 + t * 8);
                uint2 u1 = *(const uint2*)(smA + (r0 + 8) * RB + kg * 32 + t * 8);
                a[mt][0] = u0.x; a[mt][1] = u1.x; a[mt][2] = u0.y; a[mt][3] = u1.y;
            }
#pragma unroll
            for (int nt = 0; nt < 4; nt++) {
                int n = nbase1 + nt * 8 + q;
                uint2 b = *(const uint2*)(Bp + n * RB + kg * 32 + t * 8);
#pragma unroll
                for (int mt = 0; mt < 4; mt++) mmaf16(acc1[mt][nt], a[mt], b.x, b.y);
            }
        }
        __syncthreads();          // A reads done before overwrite
#pragma unroll
        for (int mt = 0; mt < 4; mt++) {
#pragma unroll
            for (int nt = 0; nt < 4; nt++) {
                int r0 = mbase + mt * 16 + q;
                int o0 = nbase1 + nt * 8 + 2 * t;
                float bb0 = __ldg(b2 + o0), bb1 = __ldg(b2 + o0 + 1);
                *(half2*)(smA + r0 * RB + ilv16(o0) * 2) = __floats2half2_rn(
                    fmaxf(acc1[mt][nt][0] + bb0, 0.0f), fmaxf(acc1[mt][nt][1] + bb1, 0.0f));
                *(half2*)(smA + (r0 + 8) * RB + ilv16(o0) * 2) = __floats2half2_rn(
                    fmaxf(acc1[mt][nt][2] + bb0, 0.0f), fmaxf(acc1[mt][nt][3] + bb1, 0.0f));
            }
        }
    }
    __syncthreads();

    // ---- phase 2: K-chunks, cp.async double-buffered B ---------------------
    const int nbase2 = ng * 40;
    for (int c = 0; c < NCH; c++) {
        if (c + 1 < NCH) {        // prefetch chunk c+1 into other buffer
            uint32_t dst = sb + (((c + 1) & 1) ? B1_OFF : B0_OFF);
            const char* src = (const char*)g_W3t + (size_t)(c + 1) * (CHN * KAH) * 2;
#pragma unroll
            for (int r = 0; r < 12; r++) {
                int idx = tid + NT * r;
                if (idx < 2880) cpa16(dst + idx * 16, src + idx * 16);
            }
            CP_COMMIT();
            CP_WAIT1();           // chunk c complete; c+1 may stay in flight
        } else {
            CP_WAIT0();
        }
        __syncthreads();

        const char* Bc = sm8 + ((c & 1) ? B1_OFF : B0_OFF);
        float acc[4][5][4];
#pragma unroll
        for (int mt = 0; mt < 4; mt++)
#pragma unroll
            for (int nt = 0; nt < 5; nt++)
#pragma unroll
                for (int x = 0; x < 4; x++) acc[mt][nt][x] = 0.0f;

#pragma unroll 3
        for (int kg = 0; kg < 9; kg++) {
            uint32_t a[4][4];
#pragma unroll
            for (int mt = 0; mt < 4; mt++) {
                int r0 = mbase + mt * 16 + q;
                uint2 u0 = *(const uint2*)(smA + r0 * RB + kg * 32 + t * 8);
                uint2 u1 = *(const uint2*)(smA + (r0 + 8) * RB + kg * 32 + t * 8);
                a[mt][0] = u0.x; a[mt][1] = u1.x; a[mt][2] = u0.y; a[mt][3] = u1.y;
            }
#pragma unroll
            for (int nt = 0; nt < 5; nt++) {
                int n = nbase2 + nt * 8 + q;
                uint2 b = *(const uint2*)(Bc + n * RB + kg * 32 + t * 8);
#pragma unroll
                for (int mt = 0; mt < 4; mt++) mmaf16(acc[mt][nt], a[mt], b.x, b.y);
            }
        }

        // epilogue: contract with v' (i-block = c*4 + ng)
        const int iblk = c * 4 + ng;
#pragma unroll
        for (int mt = 0; mt < 4; mt++) {
            int e0 = mbase + mt * 16 + q;
            float s0 = 0.0f, s1 = 0.0f;
#pragma unroll
            for (int nt = 0; nt < 5; nt++) {
                int col = nt * 8 + 2 * t;
                float2 vp0 = *(const float2*)(vs + e0 * 40 + col);
                float2 vp1 = *(const float2*)(vs + (e0 + 8) * 40 + col);
                s0 = fmaf(acc[mt][nt][0], vp0.x, s0);
                s0 = fmaf(acc[mt][nt][1], vp0.y, s0);
                s1 = fmaf(acc[mt][nt][2], vp1.x, s1);
                s1 = fmaf(acc[mt][nt][3], vp1.y, s1);
            }
            s0 += __shfl_xor_sync(0xFFFFFFFFu, s0, 1);
            s0 += __shfl_xor_sync(0xFFFFFFFFu, s0, 2);
            s1 += __shfl_xor_sync(0xFFFFFFFFu, s1, 1);
            s1 += __shfl_xor_sync(0xFFFFFFFFu, s1, 2);
            if (t == 0) {
                os[e0 * 33 + iblk]       = s0;
                os[(e0 + 8) * 33 + iblk] = s1;
            }
        }
        __syncthreads();          // B reads + os writes done before next prefetch
    }

    // ---- coalesced output --------------------------------------------------
#pragma unroll
    for (int r = 0; r < 16; r++) {
        int idx = tid + NT * r;
        int e = idx >> 5, i = idx & 31;
        out[(ebase + e) * 32 + i] = os[e * 33 + i];
    }
}

extern "C" void kernel_launch(void* const* d_in, const int* in_sizes, int n_in,
                              void* d_out, int out_size) {
    const float* pos_i = (const float*)d_in[0];
    const float* pos_j = (const float*)d_in[1];
    const float* v     = (const float*)d_in[2];
    const float* W1    = (const float*)d_in[3];
    const float* b1    = (const float*)d_in[4];
    const float* W2    = (const float*)d_in[5];
    const float* b2    = (const float*)d_in[6];
    const float* W3    = (const float*)d_in[7];
    const float* b3    = (const float*)d_in[8];
    float* out = (float*)d_out;

    prep_w2<<<(128 * KAH + NT - 1) / NT, NT>>>(W2);
    prep_w3<<<(NCH * CHN * KAH + NT - 1) / NT, NT>>>(W3, b3);

    cudaFuncSetAttribute(fnn_mma_kernel,
                         cudaFuncAttributeMaxDynamicSharedMemorySize, SMEM_BYTES);
    fnn_mma_kernel<<<E_TOTAL / TILE_E, NT, SMEM_BYTES>>>(
        pos_i, pos_j, v, W1, b1, b2, out);
}